// round 3
// baseline (speedup 1.0000x reference)
#include <cuda_runtime.h>
#include <math.h>

#define B_ 64
#define T_ 1024
#define I_ 128
#define H_ 512

#define GRID_SCAN 128
#define NT 256

// ---------------- device scratch (no allocations allowed) -------------------
__device__ float g_xp[B_ * T_ * H_];        // input projection  [B,T,H]
__device__ float g_hs[B_ * T_ * H_];        // all hidden states [B,T,H]
__device__ float g_h[B_ * H_];              // current state
__device__ float g_z1[B_ * (H_ / 2)];       // tau hidden layer
__device__ unsigned g_bar_count;
__device__ unsigned g_bar_gen;

// ---------------- scan SMEM layout (floats) ---------------------------------
#define CTX_S 1032   // 1024 + 8 pad
#define WT1_S 1032
#define WREC_S 516   // 512 + 4 pad (keeps float4 alignment)
#define WT2_S 260
#define Z1R_S 260
constexpr int P_CTX  = 0;                    // [16][1032]
constexpr int P_WT1  = P_CTX + 16 * CTX_S;   // [8][1032]  W_tau1^T slice
constexpr int P_WREC = P_WT1 + 8 * WT1_S;    // [16][516]  W_rec rows
constexpr int P_WT2  = P_WREC + 16 * WREC_S; // [16][260]  W_tau2^T slice
constexpr int P_Z1R  = P_WT2 + 16 * WT2_S;   // [16][260]  staged z1 rows
constexpr int P_SCR  = P_Z1R + 16 * Z1R_S;   // [2048]     z1 partial scratch
constexpr int P_DRV  = P_SCR + 2048;         // [256]      tanh(drive)
constexpr int P_B1   = P_DRV + 256;          // [8]
constexpr int P_BIAS = P_B1 + 8;             // [16]
constexpr int P_B2   = P_BIAS + 16;          // [16]
constexpr int SCAN_FLOATS = P_B2 + 16;
constexpr int SCAN_SMEM = SCAN_FLOATS * 4;   // ~174.8 KB

constexpr int XP_SMEM = (64 * 132 + 128 * 68) * 4;  // ~68.6 KB

// ---------------- grid barrier (all 128 CTAs resident) ----------------------
__device__ __forceinline__ void grid_barrier(unsigned& gen) {
    __syncthreads();
    if (threadIdx.x == 0) {
        __threadfence();
        unsigned target = gen + 1;
        unsigned old = atomicAdd(&g_bar_count, 1);
        if (old == GRID_SCAN - 1) {
            g_bar_count = 0;
            __threadfence();
            *(volatile unsigned*)&g_bar_gen = target;
        } else {
            while (*(volatile unsigned*)&g_bar_gen < target) { }
        }
        __threadfence();
        gen = target;
    }
    __syncthreads();
}

// ---------------- xp = x @ W_in + b_in --------------------------------------
__global__ void __launch_bounds__(256) xp_gemm(const float* __restrict__ x,
                                               const float* __restrict__ W,
                                               const float* __restrict__ bin) {
    extern __shared__ float sm[];
    float* sx = sm;                 // [64][132]
    float* sw = sm + 64 * 132;      // [128][68]
    const int tid = threadIdx.x;
    const int n0 = blockIdx.x * 64;       // output col tile
    const int r0 = blockIdx.y * 64;       // row tile (row = b*T + t)

    for (int f = tid; f < 64 * 32; f += 256) {        // x tile [64][128]
        int row = f >> 5, kq = (f & 31) << 2;
        float4 v = *(const float4*)(x + (size_t)(r0 + row) * I_ + kq);
        *(float4*)(sx + row * 132 + kq) = v;
    }
    for (int f = tid; f < 128 * 16; f += 256) {       // W tile [128][64]
        int k = f >> 4, nq = (f & 15) << 2;
        float4 v = *(const float4*)(W + (size_t)k * H_ + n0 + nq);
        *(float4*)(sw + k * 68 + nq) = v;
    }
    __syncthreads();

    const int ty = tid >> 4, tx = tid & 15;
    float acc[4][4];
#pragma unroll
    for (int i = 0; i < 4; i++)
#pragma unroll
        for (int j = 0; j < 4; j++) acc[i][j] = 0.f;

#pragma unroll 8
    for (int k = 0; k < 128; k++) {
        float a[4];
#pragma unroll
        for (int i = 0; i < 4; i++) a[i] = sx[(ty * 4 + i) * 132 + k];
        float4 w = *(const float4*)(sw + k * 68 + tx * 4);
#pragma unroll
        for (int i = 0; i < 4; i++) {
            acc[i][0] += a[i] * w.x;
            acc[i][1] += a[i] * w.y;
            acc[i][2] += a[i] * w.z;
            acc[i][3] += a[i] * w.w;
        }
    }

    float4 bv = *(const float4*)(bin + n0 + tx * 4);
#pragma unroll
    for (int i = 0; i < 4; i++) {
        float4 r;
        r.x = acc[i][0] + bv.x;
        r.y = acc[i][1] + bv.y;
        r.z = acc[i][2] + bv.z;
        r.w = acc[i][3] + bv.w;
        *(float4*)(g_xp + (size_t)(r0 + ty * 4 + i) * H_ + n0 + tx * 4) = r;
    }
}

// ---------------- persistent scan -------------------------------------------
__global__ void __launch_bounds__(NT, 1) scan_kernel(
    const float* __restrict__ W_rec, const float* __restrict__ bias,
    const float* __restrict__ W_tau1, const float* __restrict__ b_tau1,
    const float* __restrict__ W_tau2, const float* __restrict__ b_tau2) {
    extern __shared__ float sm[];
    const int tid = threadIdx.x;
    const int cg = blockIdx.x & 31;   // col group
    const int bg = blockIdx.x >> 5;   // batch group
    const int r0 = bg * 16;           // 16 batch rows
    const int zc0 = cg * 8;           // 8 z1 cols
    const int hc0 = cg * 16;          // 16 h cols

    unsigned gen = 0;
    if (tid == 0) gen = *(volatile unsigned*)&g_bar_gen;

    // ---- load weight slices into SMEM (once) ----
    for (int e = tid; e < 8 * 1024; e += NT) {          // W_tau1^T [8 cols][1024]
        int c = e >> 10, k = e & 1023;
        sm[P_WT1 + c * WT1_S + k] = __ldg(&W_tau1[(size_t)k * (H_ / 2) + zc0 + c]);
    }
    for (int e = tid; e < 16 * 512; e += NT) {          // W_rec rows [16][512]
        int c = e >> 9, k = e & 511;
        sm[P_WREC + c * WREC_S + k] = __ldg(&W_rec[(size_t)(hc0 + c) * H_ + k]);
    }
    for (int e = tid; e < 16 * 256; e += NT) {          // W_tau2^T [16 cols][256]
        int c = e >> 8, k = e & 255;
        sm[P_WT2 + c * WT2_S + k] = __ldg(&W_tau2[(size_t)k * H_ + hc0 + c]);
    }
    if (tid < 8)  sm[P_B1 + tid] = b_tau1[zc0 + tid];
    if (tid < 16) sm[P_BIAS + tid] = bias[hc0 + tid];
    if (tid < 16) sm[P_B2 + tid] = b_tau2[hc0 + tid];
    // zero this CTA's h slice
    {
        int r = tid >> 4, c = tid & 15;
        __stcg(&g_h[(r0 + r) * H_ + hc0 + c], 0.f);
    }
    grid_barrier(gen);

    const int rr = tid >> 4, cc = tid & 15;   // drive/tau mapping

    for (int t = 0; t < T_; t++) {
        // ---- phase A: stage ctx = [xp_t | h] for 16 rows ----
#pragma unroll
        for (int i = 0; i < 16; i++) {
            int col = tid * 4;   // tid<128 -> xp half, else h half
            float4 v;
            if (tid < 128)
                v = *(const float4*)&g_xp[((size_t)(r0 + i) * T_ + t) * H_ + col];
            else
                v = __ldcg((const float4*)&g_h[(r0 + i) * H_ + (col - 512)]);
            *(float4*)&sm[P_CTX + i * CTX_S + col] = v;
        }
        __syncthreads();

        // ---- z1 partials: 16 tiles of 4 rows x 2 cols, 16-way k-split ----
        {
            const int ks = tid & 15, tile = tid >> 4;
            const int rt = (tile & 3) * 4, ct = (tile >> 2) * 2;
            float acc[4][2];
#pragma unroll
            for (int i = 0; i < 4; i++) { acc[i][0] = 0.f; acc[i][1] = 0.f; }
            const float* ctx0 = &sm[P_CTX + rt * CTX_S];
            const float* w0 = &sm[P_WT1 + ct * WT1_S];
            const int k0 = ks * 64;
#pragma unroll 4
            for (int k = k0; k < k0 + 64; k += 4) {
                float4 wa = *(const float4*)&w0[k];
                float4 wb = *(const float4*)&w0[WT1_S + k];
#pragma unroll
                for (int i = 0; i < 4; i++) {
                    float4 a = *(const float4*)&ctx0[i * CTX_S + k];
                    acc[i][0] += a.x * wa.x + a.y * wa.y + a.z * wa.z + a.w * wa.w;
                    acc[i][1] += a.x * wb.x + a.y * wb.y + a.z * wb.z + a.w * wb.w;
                }
            }
#pragma unroll
            for (int i = 0; i < 4; i++) {
                sm[P_SCR + tid * 8 + i * 2 + 0] = acc[i][0];
                sm[P_SCR + tid * 8 + i * 2 + 1] = acc[i][1];
            }
        }

        // ---- drive: thread (rr, cc) -> tanh(xt + h.W_rec_row + bias) ----
        {
            float4 a4 = make_float4(0.f, 0.f, 0.f, 0.f);
            const float* hrow = &sm[P_CTX + rr * CTX_S + 512];
            const float* wr = &sm[P_WREC + cc * WREC_S];
#pragma unroll 4
            for (int k = 0; k < 512; k += 4) {
                float4 a = *(const float4*)&hrow[k];
                float4 w = *(const float4*)&wr[k];
                a4.x += a.x * w.x; a4.y += a.y * w.y;
                a4.z += a.z * w.z; a4.w += a.w * w.w;
            }
            float pre = (a4.x + a4.y) + (a4.z + a4.w)
                      + sm[P_BIAS + cc] + sm[P_CTX + rr * CTX_S + hc0 + cc];
            float e2 = __expf(2.f * pre);
            sm[P_DRV + rr * 16 + cc] = 1.f - 2.f / (e2 + 1.f);
        }
        __syncthreads();

        // ---- z1 reduce + relu + global store ----
        if (tid < 128) {
            int r = tid >> 3, c = tid & 7;
            int tile = (r >> 2) + (c >> 1) * 4;
            int e = (r & 3) * 2 + (c & 1);
            float s = 0.f;
#pragma unroll
            for (int ks = 0; ks < 16; ks++) s += sm[P_SCR + (tile * 16 + ks) * 8 + e];
            s += sm[P_B1 + c];
            __stcg(&g_z1[(r0 + r) * (H_ / 2) + zc0 + c], fmaxf(s, 0.f));
        }
        grid_barrier(gen);

        // ---- phase B: stage full z1 rows (written by all 32 col groups) ----
#pragma unroll
        for (int i = 0; i < 4; i++) {
            int idx = tid + i * 256;        // float4 index, 64 per row
            int row = idx >> 6, c4 = idx & 63;
            float4 v = __ldcg((const float4*)&g_z1[(r0 + row) * (H_ / 2) + c4 * 4]);
            *(float4*)&sm[P_Z1R + row * Z1R_S + c4 * 4] = v;
        }
        __syncthreads();

        // ---- tau + Euler update ----
        {
            float4 a4 = make_float4(0.f, 0.f, 0.f, 0.f);
            const float* zr = &sm[P_Z1R + rr * Z1R_S];
            const float* w2 = &sm[P_WT2 + cc * WT2_S];
#pragma unroll 4
            for (int k = 0; k < 256; k += 4) {
                float4 a = *(const float4*)&zr[k];
                float4 w = *(const float4*)&w2[k];
                a4.x += a.x * w.x; a4.y += a.y * w.y;
                a4.z += a.z * w.z; a4.w += a.w * w.w;
            }
            float xv = (a4.x + a4.y) + (a4.z + a4.w) + sm[P_B2 + cc];
            float sig = 1.f / (1.f + __expf(-xv));
            float tau = 5.f + sig * 45.f;
            float hold = sm[P_CTX + rr * CTX_S + 512 + hc0 + cc];
            float hnew = hold + (sm[P_DRV + rr * 16 + cc] - hold) / tau;
            __stcg(&g_h[(r0 + rr) * H_ + hc0 + cc], hnew);
            g_hs[((size_t)(r0 + rr) * T_ + t) * H_ + hc0 + cc] = hnew;
        }
        grid_barrier(gen);
    }
}

// ---------------- out = hs @ W_out + b_out ----------------------------------
__global__ void __launch_bounds__(256) out_gemm(const float* __restrict__ W_out,
                                                const float* __restrict__ b_out,
                                                float* __restrict__ out) {
    __shared__ float sw[H_ * 10];
    __shared__ float sb[10];
    for (int e = threadIdx.x; e < H_ * 10; e += 256) sw[e] = W_out[e];
    if (threadIdx.x < 10) sb[threadIdx.x] = b_out[threadIdx.x];
    __syncthreads();

    int wid = threadIdx.x >> 5, lane = threadIdx.x & 31;
    for (int row = blockIdx.x * 8 + wid; row < B_ * T_; row += gridDim.x * 8) {
        float h[16];
        const float* hp = &g_hs[(size_t)row * H_ + lane * 16];
#pragma unroll
        for (int i = 0; i < 4; i++) {
            float4 v = *(const float4*)&hp[i * 4];
            h[i * 4 + 0] = v.x; h[i * 4 + 1] = v.y;
            h[i * 4 + 2] = v.z; h[i * 4 + 3] = v.w;
        }
#pragma unroll
        for (int o = 0; o < 10; o++) {
            float p = 0.f;
#pragma unroll
            for (int i = 0; i < 16; i++) p += h[i] * sw[(lane * 16 + i) * 10 + o];
            p += __shfl_xor_sync(0xffffffff, p, 16);
            p += __shfl_xor_sync(0xffffffff, p, 8);
            p += __shfl_xor_sync(0xffffffff, p, 4);
            p += __shfl_xor_sync(0xffffffff, p, 2);
            p += __shfl_xor_sync(0xffffffff, p, 1);
            if (lane == 0) out[row * 10 + o] = p + sb[o];
        }
    }
}

// ---------------- launch -----------------------------------------------------
extern "C" void kernel_launch(void* const* d_in, const int* in_sizes, int n_in,
                              void* d_out, int out_size) {
    const float* x      = (const float*)d_in[0];
    const float* W_in   = (const float*)d_in[1];
    const float* b_in   = (const float*)d_in[2];
    const float* W_rec  = (const float*)d_in[3];
    const float* bias   = (const float*)d_in[4];
    const float* W_tau1 = (const float*)d_in[5];
    const float* b_tau1 = (const float*)d_in[6];
    const float* W_tau2 = (const float*)d_in[7];
    const float* b_tau2 = (const float*)d_in[8];
    const float* W_out  = (const float*)d_in[9];
    const float* b_out  = (const float*)d_in[10];
    float* out = (float*)d_out;

    cudaFuncSetAttribute(xp_gemm, cudaFuncAttributeMaxDynamicSharedMemorySize, XP_SMEM);
    cudaFuncSetAttribute(scan_kernel, cudaFuncAttributeMaxDynamicSharedMemorySize, SCAN_SMEM);

    xp_gemm<<<dim3(8, 1024), 256, XP_SMEM>>>(x, W_in, b_in);
    scan_kernel<<<GRID_SCAN, NT, SCAN_SMEM>>>(W_rec, bias, W_tau1, b_tau1,
                                              W_tau2, b_tau2);
    out_gemm<<<2048, 256>>>(W_out, b_out, out);
}

// round 4
// speedup vs baseline: 1.7882x; 1.7882x over previous
#include <cuda_runtime.h>
#include <math.h>

#define B_ 64
#define T_ 1024
#define I_ 128
#define H_ 512

#define CLUSTER 16
#define GRID_SCAN 128
#define NT 256

// ---------------- device scratch (no allocations allowed) -------------------
__device__ float g_xp[B_ * T_ * H_];        // input projection  [B,T,H]
__device__ float g_hs[B_ * T_ * H_];        // all hidden states [B,T,H]
__device__ float g_h[B_ * H_];              // current state
__device__ float g_z1[B_ * (H_ / 2)];       // tau hidden layer

// ---------------- scan SMEM layout (floats) ---------------------------------
// strides chosen so row-stride in 16B units is odd (minimal bank phases) and
// every row base stays 16B-aligned.
#define CTX_S  1032
#define WT1_S  1028
#define WREC_S 516
#define WT2_S  260
#define Z1_S   264
constexpr int P_CTX  = 0;                     // [8][1032]   ctx = [xp | h]
constexpr int P_WT1  = P_CTX + 8 * CTX_S;     // [16][1028]  W_tau1^T slice
constexpr int P_WREC = P_WT1 + 16 * WT1_S;    // [32][516]   W_rec rows
constexpr int P_WT2  = P_WREC + 32 * WREC_S;  // [32][260]   W_tau2^T slice
constexpr int P_Z1   = P_WT2 + 32 * WT2_S;    // [8][264]    staged full z1
constexpr int P_SCR  = P_Z1 + 8 * Z1_S;       // [2048] z1 partials [16s][8r][16c]
constexpr int P_SCR2 = P_SCR + 2048;          // [2048] drive/tau partials [8s][8r][32c]
constexpr int P_B1   = P_SCR2 + 2048;         // [16]
constexpr int P_BIAS = P_B1 + 16;             // [32]
constexpr int P_B2   = P_BIAS + 32;           // [32]
constexpr int SCAN_FLOATS = P_B2 + 32;
constexpr int SCAN_SMEM = SCAN_FLOATS * 4;    // ~223 KB

constexpr int XP_SMEM = (64 * 132 + 128 * 68) * 4;  // ~68.6 KB

// ---------------- helpers ----------------------------------------------------
__device__ __forceinline__ void fma2(unsigned long long& d,
                                     unsigned long long a,
                                     unsigned long long b) {
    asm("fma.rn.f32x2 %0, %1, %2, %0;" : "+l"(d) : "l"(a), "l"(b));
}
__device__ __forceinline__ float pair_sum(unsigned long long v) {
    return __uint_as_float((unsigned)v) + __uint_as_float((unsigned)(v >> 32));
}
#define CLUSTER_SYNC() do { \
    asm volatile("barrier.cluster.arrive.aligned;" ::: "memory"); \
    asm volatile("barrier.cluster.wait.aligned;"   ::: "memory"); \
} while (0)

// ---------------- xp = x @ W_in + b_in --------------------------------------
__global__ void __launch_bounds__(256) xp_gemm(const float* __restrict__ x,
                                               const float* __restrict__ W,
                                               const float* __restrict__ bin) {
    extern __shared__ float sm[];
    float* sx = sm;                 // [64][132]
    float* sw = sm + 64 * 132;      // [128][68]
    const int tid = threadIdx.x;
    const int n0 = blockIdx.x * 64;
    const int r0 = blockIdx.y * 64;

    for (int f = tid; f < 64 * 32; f += 256) {
        int row = f >> 5, kq = (f & 31) << 2;
        float4 v = *(const float4*)(x + (size_t)(r0 + row) * I_ + kq);
        *(float4*)(sx + row * 132 + kq) = v;
    }
    for (int f = tid; f < 128 * 16; f += 256) {
        int k = f >> 4, nq = (f & 15) << 2;
        float4 v = *(const float4*)(W + (size_t)k * H_ + n0 + nq);
        *(float4*)(sw + k * 68 + nq) = v;
    }
    __syncthreads();

    const int ty = tid >> 4, tx = tid & 15;
    float acc[4][4];
#pragma unroll
    for (int i = 0; i < 4; i++)
#pragma unroll
        for (int j = 0; j < 4; j++) acc[i][j] = 0.f;

#pragma unroll 8
    for (int k = 0; k < 128; k++) {
        float a[4];
#pragma unroll
        for (int i = 0; i < 4; i++) a[i] = sx[(ty * 4 + i) * 132 + k];
        float4 w = *(const float4*)(sw + k * 68 + tx * 4);
#pragma unroll
        for (int i = 0; i < 4; i++) {
            acc[i][0] += a[i] * w.x;
            acc[i][1] += a[i] * w.y;
            acc[i][2] += a[i] * w.z;
            acc[i][3] += a[i] * w.w;
        }
    }

    float4 bv = *(const float4*)(bin + n0 + tx * 4);
#pragma unroll
    for (int i = 0; i < 4; i++) {
        float4 r;
        r.x = acc[i][0] + bv.x;
        r.y = acc[i][1] + bv.y;
        r.z = acc[i][2] + bv.z;
        r.w = acc[i][3] + bv.w;
        *(float4*)(g_xp + (size_t)(r0 + ty * 4 + i) * H_ + n0 + tx * 4) = r;
    }
}

// ---------------- persistent clustered scan ----------------------------------
__global__ void __launch_bounds__(NT, 1) __cluster_dims__(CLUSTER, 1, 1)
scan_kernel(const float* __restrict__ W_rec, const float* __restrict__ bias,
            const float* __restrict__ W_tau1, const float* __restrict__ b_tau1,
            const float* __restrict__ W_tau2, const float* __restrict__ b_tau2) {
    extern __shared__ float sm[];
    const int tid = threadIdx.x;
    const int cid = blockIdx.x & (CLUSTER - 1);   // rank in cluster (col group)
    const int bg  = blockIdx.x >> 4;              // batch group (cluster id)
    const int r0  = bg * 8;                       // 8 batch rows
    const int hc0 = cid * 32;                     // 32 h cols
    const int zc0 = cid * 16;                     // 16 z1 cols

    // ---- load weight slices into SMEM (once) ----
    for (int e = tid; e < 16 * 1024; e += NT) {   // W_tau1^T [16][1024]
        int c = e >> 10, k = e & 1023;
        sm[P_WT1 + c * WT1_S + k] = __ldg(&W_tau1[(size_t)k * (H_ / 2) + zc0 + c]);
    }
    for (int e = tid; e < 32 * 512; e += NT) {    // W_rec rows [32][512]
        int c = e >> 9, k = e & 511;
        sm[P_WREC + c * WREC_S + k] = __ldg(&W_rec[(size_t)(hc0 + c) * H_ + k]);
    }
    for (int e = tid; e < 32 * 256; e += NT) {    // W_tau2^T [32][256]
        int c = e >> 8, k = e & 255;
        sm[P_WT2 + c * WT2_S + k] = __ldg(&W_tau2[(size_t)k * H_ + hc0 + c]);
    }
    if (tid < 16) sm[P_B1 + tid]   = b_tau1[zc0 + tid];
    if (tid < 32) sm[P_BIAS + tid] = bias[hc0 + tid];
    if (tid < 32) sm[P_B2 + tid]   = b_tau2[hc0 + tid];
    // zero this CTA's h slice (8 rows x 32 cols)
    {
        int r = tid >> 5, c = tid & 31;
        __stcg(&g_h[(r0 + r) * H_ + hc0 + c], 0.f);
    }
    __syncthreads();
    CLUSTER_SYNC();

    const int rr = tid >> 5;          // 0..7 row
    const int cc = tid & 31;          // 0..31 col (drive/tau)

    for (int t = 0; t < T_; t++) {
        // ---- phase A0: stage ctx = [xp_t(512) | h(512)] for 8 rows ----
#pragma unroll
        for (int j = 0; j < 8; j++) {
            float4 v;
            if (tid < 128)
                v = __ldcg((const float4*)&g_xp[((size_t)(r0 + j) * T_ + t) * H_ + tid * 4]);
            else
                v = __ldcg((const float4*)&g_h[(r0 + j) * H_ + (tid - 128) * 4]);
            *(float4*)&sm[P_CTX + j * CTX_S + tid * 4] = v;
        }
        __syncthreads();

        // ---- A1: z1 partials. thread = (z1 col c16, ksplit s16 of 64) ----
        {
            const int c16 = tid & 15, s = tid >> 4;
            const int k0 = s * 64;
            unsigned long long acc[8];
#pragma unroll
            for (int r = 0; r < 8; r++) acc[r] = 0ull;
            const float* wp = &sm[P_WT1 + c16 * WT1_S];
#pragma unroll 4
            for (int k = k0; k < k0 + 64; k += 4) {
                double2 w = *(const double2*)&wp[k];
                unsigned long long w01 = __double_as_longlong(w.x);
                unsigned long long w23 = __double_as_longlong(w.y);
#pragma unroll
                for (int r = 0; r < 8; r++) {
                    double2 a = *(const double2*)&sm[P_CTX + r * CTX_S + k];
                    fma2(acc[r], __double_as_longlong(a.x), w01);
                    fma2(acc[r], __double_as_longlong(a.y), w23);
                }
            }
#pragma unroll
            for (int r = 0; r < 8; r++)
                sm[P_SCR + s * 128 + r * 16 + c16] = pair_sum(acc[r]);
        }

        // ---- A2: drive partials. thread = (h col cc, ksplit s8 of 64) ----
        {
            const int s = tid >> 5;
            const int k0 = s * 64;
            unsigned long long acc[8];
#pragma unroll
            for (int r = 0; r < 8; r++) acc[r] = 0ull;
            const float* wp = &sm[P_WREC + cc * WREC_S];
#pragma unroll 4
            for (int k = k0; k < k0 + 64; k += 4) {
                double2 w = *(const double2*)&wp[k];
                unsigned long long w01 = __double_as_longlong(w.x);
                unsigned long long w23 = __double_as_longlong(w.y);
#pragma unroll
                for (int r = 0; r < 8; r++) {
                    double2 a = *(const double2*)&sm[P_CTX + r * CTX_S + 512 + k];
                    fma2(acc[r], __double_as_longlong(a.x), w01);
                    fma2(acc[r], __double_as_longlong(a.y), w23);
                }
            }
#pragma unroll
            for (int r = 0; r < 8; r++)
                sm[P_SCR2 + s * 256 + r * 32 + cc] = pair_sum(acc[r]);
        }
        __syncthreads();

        // ---- A3: reductions ----
        float drv;
        {
            float s2 = 0.f;
#pragma unroll
            for (int s = 0; s < 8; s++) s2 += sm[P_SCR2 + s * 256 + rr * 32 + cc];
            float pre = s2 + sm[P_BIAS + cc] + sm[P_CTX + rr * CTX_S + hc0 + cc];
            float e2 = __expf(2.f * pre);
            drv = 1.f - 2.f / (e2 + 1.f);
        }
        if (tid < 128) {
            int r = tid >> 4, c = tid & 15;
            float s2 = 0.f;
#pragma unroll
            for (int s = 0; s < 16; s++) s2 += sm[P_SCR + s * 128 + r * 16 + c];
            s2 += sm[P_B1 + c];
            __stcg(&g_z1[(r0 + r) * (H_ / 2) + zc0 + c], fmaxf(s2, 0.f));
        }
        CLUSTER_SYNC();   // z1 slices visible cluster-wide

        // ---- B0: stage full z1 rows [8][256] ----
#pragma unroll
        for (int i = 0; i < 2; i++) {
            int idx = tid * 2 + i;               // float4 index, 64 per row
            int row = idx >> 6, q = idx & 63;
            float4 v = __ldcg((const float4*)&g_z1[(r0 + row) * (H_ / 2) + q * 4]);
            *(float4*)&sm[P_Z1 + row * Z1_S + q * 4] = v;
        }
        __syncthreads();

        // ---- B1: tau partials. thread = (h col cc, ksplit s8 of 32) ----
        {
            const int s = tid >> 5;
            const int k0 = s * 32;
            unsigned long long acc[8];
#pragma unroll
            for (int r = 0; r < 8; r++) acc[r] = 0ull;
            const float* wp = &sm[P_WT2 + cc * WT2_S];
#pragma unroll
            for (int k = k0; k < k0 + 32; k += 4) {
                double2 w = *(const double2*)&wp[k];
                unsigned long long w01 = __double_as_longlong(w.x);
                unsigned long long w23 = __double_as_longlong(w.y);
#pragma unroll
                for (int r = 0; r < 8; r++) {
                    double2 a = *(const double2*)&sm[P_Z1 + r * Z1_S + k];
                    fma2(acc[r], __double_as_longlong(a.x), w01);
                    fma2(acc[r], __double_as_longlong(a.y), w23);
                }
            }
#pragma unroll
            for (int r = 0; r < 8; r++)
                sm[P_SCR2 + s * 256 + r * 32 + cc] = pair_sum(acc[r]);
        }
        __syncthreads();

        // ---- B2: tau reduce + Euler update ----
        {
            float s2 = 0.f;
#pragma unroll
            for (int s = 0; s < 8; s++) s2 += sm[P_SCR2 + s * 256 + rr * 32 + cc];
            s2 += sm[P_B2 + cc];
            float sig = 1.f / (1.f + __expf(-s2));
            float tau = 5.f + sig * 45.f;
            float hold = sm[P_CTX + rr * CTX_S + 512 + hc0 + cc];
            float hnew = hold + (drv - hold) / tau;
            __stcg(&g_h[(r0 + rr) * H_ + hc0 + cc], hnew);
            __stcg(&g_hs[((size_t)(r0 + rr) * T_ + t) * H_ + hc0 + cc], hnew);
        }
        CLUSTER_SYNC();   // h finalized before next step's staging
    }
}

// ---------------- out = hs @ W_out + b_out ----------------------------------
__global__ void __launch_bounds__(256) out_gemm(const float* __restrict__ W_out,
                                                const float* __restrict__ b_out,
                                                float* __restrict__ out) {
    __shared__ float sw[H_ * 10];
    __shared__ float sb[10];
    for (int e = threadIdx.x; e < H_ * 10; e += 256) sw[e] = W_out[e];
    if (threadIdx.x < 10) sb[threadIdx.x] = b_out[threadIdx.x];
    __syncthreads();

    int wid = threadIdx.x >> 5, lane = threadIdx.x & 31;
    for (int row = blockIdx.x * 8 + wid; row < B_ * T_; row += gridDim.x * 8) {
        float h[16];
        const float* hp = &g_hs[(size_t)row * H_ + lane * 16];
#pragma unroll
        for (int i = 0; i < 4; i++) {
            float4 v = *(const float4*)&hp[i * 4];
            h[i * 4 + 0] = v.x; h[i * 4 + 1] = v.y;
            h[i * 4 + 2] = v.z; h[i * 4 + 3] = v.w;
        }
#pragma unroll
        for (int o = 0; o < 10; o++) {
            float p = 0.f;
#pragma unroll
            for (int i = 0; i < 16; i++) p += h[i] * sw[(lane * 16 + i) * 10 + o];
            p += __shfl_xor_sync(0xffffffff, p, 16);
            p += __shfl_xor_sync(0xffffffff, p, 8);
            p += __shfl_xor_sync(0xffffffff, p, 4);
            p += __shfl_xor_sync(0xffffffff, p, 2);
            p += __shfl_xor_sync(0xffffffff, p, 1);
            if (lane == 0) out[row * 10 + o] = p + sb[o];
        }
    }
}

// ---------------- launch -----------------------------------------------------
extern "C" void kernel_launch(void* const* d_in, const int* in_sizes, int n_in,
                              void* d_out, int out_size) {
    const float* x      = (const float*)d_in[0];
    const float* W_in   = (const float*)d_in[1];
    const float* b_in   = (const float*)d_in[2];
    const float* W_rec  = (const float*)d_in[3];
    const float* bias   = (const float*)d_in[4];
    const float* W_tau1 = (const float*)d_in[5];
    const float* b_tau1 = (const float*)d_in[6];
    const float* W_tau2 = (const float*)d_in[7];
    const float* b_tau2 = (const float*)d_in[8];
    const float* W_out  = (const float*)d_in[9];
    const float* b_out  = (const float*)d_in[10];
    float* out = (float*)d_out;

    cudaFuncSetAttribute(xp_gemm, cudaFuncAttributeMaxDynamicSharedMemorySize, XP_SMEM);
    cudaFuncSetAttribute(scan_kernel, cudaFuncAttributeMaxDynamicSharedMemorySize, SCAN_SMEM);
    cudaFuncSetAttribute(scan_kernel, cudaFuncAttributeNonPortableClusterSizeAllowed, 1);

    xp_gemm<<<dim3(8, 1024), 256, XP_SMEM>>>(x, W_in, b_in);
    scan_kernel<<<GRID_SCAN, NT, SCAN_SMEM>>>(W_rec, bias, W_tau1, b_tau1,
                                              W_tau2, b_tau2);
    out_gemm<<<2048, 256>>>(W_out, b_out, out);
}

// round 5
// speedup vs baseline: 2.0593x; 1.1516x over previous
#include <cuda_runtime.h>
#include <math.h>

#define B_ 64
#define T_ 1024
#define I_ 128
#define H_ 512

#define CLUSTER 16
#define GRID_SCAN 128
#define NT 256

// ---------------- device scratch (no allocations allowed) -------------------
__device__ float g_xp[B_ * T_ * H_];        // x @ W_in + b_in        [B,T,512]
__device__ float g_xq[B_ * T_ * (H_ / 2)];  // x @ W_eff + b_eff      [B,T,256]
__device__ float g_hs[B_ * T_ * H_];        // all hidden states      [B,T,512]
__device__ float g_h[B_ * H_];              // current state
__device__ float g_z1[B_ * (H_ / 2)];       // tau hidden layer
__device__ float g_weff[I_ * (H_ / 2)];     // W_in @ W_tau1[:512]    [128,256]
__device__ float g_beff[H_ / 2];            // b_in @ W1x + b_tau1    [256]

// ---------------- scan SMEM layout (floats) ---------------------------------
// strides: 516 mod 32 = 4, 260 mod 32 = 4 -> rows 0..7 land on distinct bank
// phases; all row bases 16B-aligned.
#define H_S   516
#define W1_S  516
#define WR_S  516
#define W2_S  260
#define Z1_S  260
#define XD_S  36
#define XQ_S  20
constexpr int P_H    = 0;                     // [8][516]   staged h
constexpr int P_WT1  = P_H + 8 * H_S;         // [16][516]  W_tau1 h-part ^T
constexpr int P_WREC = P_WT1 + 16 * W1_S;     // [32][516]  W_rec rows
constexpr int P_WT2  = P_WREC + 32 * WR_S;    // [32][260]  W_tau2 ^T
constexpr int P_Z1   = P_WT2 + 32 * W2_S;     // [8][260]   staged full z1
constexpr int P_XD   = P_Z1 + 8 * Z1_S;       // [8][36]    xp diag slice
constexpr int P_XQ   = P_XD + 8 * XD_S;       // [8][20]    xq slice
constexpr int P_SCR  = P_XQ + 8 * XQ_S;       // [4128]     shared partials
constexpr int P_B1   = P_SCR + 4128;          // [16]
constexpr int P_BIAS = P_B1 + 16;             // [32]
constexpr int P_B2   = P_BIAS + 32;           // [32]
constexpr int SCAN_FLOATS = P_B2 + 32;
constexpr int SCAN_SMEM = SCAN_FLOATS * 4;    // ~171.7 KB

constexpr int XP_SMEM = (64 * 132 + 128 * 68) * 4;  // ~68.6 KB

// ---------------- helpers ----------------------------------------------------
__device__ __forceinline__ void fma2(unsigned long long& d,
                                     unsigned long long a,
                                     unsigned long long b) {
    asm("fma.rn.f32x2 %0, %1, %2, %0;" : "+l"(d) : "l"(a), "l"(b));
}
__device__ __forceinline__ float pair_sum(unsigned long long v) {
    return __uint_as_float((unsigned)v) + __uint_as_float((unsigned)(v >> 32));
}
#define CLUSTER_SYNC() do { \
    asm volatile("barrier.cluster.arrive.aligned;" ::: "memory"); \
    asm volatile("barrier.cluster.wait.aligned;"   ::: "memory"); \
} while (0)

// ---------------- W_eff = W_in @ W_tau1[:512,:] ------------------------------
__global__ void __launch_bounds__(256) weff_gemm(const float* __restrict__ Win,
                                                 const float* __restrict__ Wt1) {
    __shared__ float sa[64 * 68];
    __shared__ float sb[64 * 68];
    const int tid = threadIdx.x;
    const int n0 = blockIdx.x * 64, m0 = blockIdx.y * 64;
    const int ty = tid >> 4, tx = tid & 15;
    float acc[4][4];
#pragma unroll
    for (int i = 0; i < 4; i++)
#pragma unroll
        for (int j = 0; j < 4; j++) acc[i][j] = 0.f;

    for (int kt = 0; kt < 512; kt += 64) {
        for (int f = tid; f < 64 * 16; f += 256) {
            int r = f >> 4, q = (f & 15) << 2;
            *(float4*)&sa[r * 68 + q] = *(const float4*)&Win[(size_t)(m0 + r) * 512 + kt + q];
            *(float4*)&sb[r * 68 + q] = *(const float4*)&Wt1[(size_t)(kt + r) * 256 + n0 + q];
        }
        __syncthreads();
#pragma unroll 8
        for (int k = 0; k < 64; k++) {
            float a[4];
#pragma unroll
            for (int i = 0; i < 4; i++) a[i] = sa[(ty * 4 + i) * 68 + k];
            float4 w = *(const float4*)&sb[k * 68 + tx * 4];
#pragma unroll
            for (int i = 0; i < 4; i++) {
                acc[i][0] += a[i] * w.x; acc[i][1] += a[i] * w.y;
                acc[i][2] += a[i] * w.z; acc[i][3] += a[i] * w.w;
            }
        }
        __syncthreads();
    }
#pragma unroll
    for (int i = 0; i < 4; i++) {
        float4 r;
        r.x = acc[i][0]; r.y = acc[i][1]; r.z = acc[i][2]; r.w = acc[i][3];
        *(float4*)&g_weff[(size_t)(m0 + ty * 4 + i) * 256 + n0 + tx * 4] = r;
    }
}

// ---------------- b_eff = b_in @ W1x + b_tau1 --------------------------------
__global__ void __launch_bounds__(64) beff_kernel(const float* __restrict__ b_in,
                                                  const float* __restrict__ Wt1,
                                                  const float* __restrict__ b_tau1) {
    __shared__ float red[64];
    const int c = blockIdx.x, lane = threadIdx.x;
    float p = 0.f;
    for (int k = lane; k < 512; k += 64) p += b_in[k] * Wt1[(size_t)k * 256 + c];
    red[lane] = p;
    __syncthreads();
    if (lane < 32) {
        float v = red[lane] + red[lane + 32];
        v += __shfl_xor_sync(0xffffffff, v, 16);
        v += __shfl_xor_sync(0xffffffff, v, 8);
        v += __shfl_xor_sync(0xffffffff, v, 4);
        v += __shfl_xor_sync(0xffffffff, v, 2);
        v += __shfl_xor_sync(0xffffffff, v, 1);
        if (lane == 0) g_beff[c] = v + b_tau1[c];
    }
}

// ---------------- generic 64-col projection: out = x @ W + b ----------------
template <int NCOLS>
__global__ void __launch_bounds__(256) proj_gemm(const float* __restrict__ x,
                                                 const float* __restrict__ W,
                                                 const float* __restrict__ bvec,
                                                 float* __restrict__ outp) {
    extern __shared__ float sm[];
    float* sx = sm;                 // [64][132]
    float* sw = sm + 64 * 132;      // [128][68]
    const int tid = threadIdx.x;
    const int n0 = blockIdx.x * 64;
    const int r0 = blockIdx.y * 64;

    for (int f = tid; f < 64 * 32; f += 256) {
        int row = f >> 5, kq = (f & 31) << 2;
        *(float4*)(sx + row * 132 + kq) =
            *(const float4*)(x + (size_t)(r0 + row) * I_ + kq);
    }
    for (int f = tid; f < 128 * 16; f += 256) {
        int k = f >> 4, nq = (f & 15) << 2;
        *(float4*)(sw + k * 68 + nq) =
            *(const float4*)(W + (size_t)k * NCOLS + n0 + nq);
    }
    __syncthreads();

    const int ty = tid >> 4, tx = tid & 15;
    float acc[4][4];
#pragma unroll
    for (int i = 0; i < 4; i++)
#pragma unroll
        for (int j = 0; j < 4; j++) acc[i][j] = 0.f;

#pragma unroll 8
    for (int k = 0; k < 128; k++) {
        float a[4];
#pragma unroll
        for (int i = 0; i < 4; i++) a[i] = sx[(ty * 4 + i) * 132 + k];
        float4 w = *(const float4*)(sw + k * 68 + tx * 4);
#pragma unroll
        for (int i = 0; i < 4; i++) {
            acc[i][0] += a[i] * w.x; acc[i][1] += a[i] * w.y;
            acc[i][2] += a[i] * w.z; acc[i][3] += a[i] * w.w;
        }
    }

    float4 bv = *(const float4*)(bvec + n0 + tx * 4);
#pragma unroll
    for (int i = 0; i < 4; i++) {
        float4 r;
        r.x = acc[i][0] + bv.x; r.y = acc[i][1] + bv.y;
        r.z = acc[i][2] + bv.z; r.w = acc[i][3] + bv.w;
        *(float4*)(outp + (size_t)(r0 + ty * 4 + i) * NCOLS + n0 + tx * 4) = r;
    }
}

// ---------------- persistent clustered scan ----------------------------------
__global__ void __launch_bounds__(NT, 1) __cluster_dims__(CLUSTER, 1, 1)
scan_kernel(const float* __restrict__ W_rec, const float* __restrict__ bias,
            const float* __restrict__ W_tau1, const float* __restrict__ b_tau1,
            const float* __restrict__ W_tau2, const float* __restrict__ b_tau2) {
    extern __shared__ float sm[];
    const int tid = threadIdx.x;
    const int cid = blockIdx.x & (CLUSTER - 1);
    const int bg  = blockIdx.x >> 4;
    const int r0  = bg * 8;
    const int hc0 = cid * 32;
    const int zc0 = cid * 16;

    // ---- one-time weight staging ----
    for (int e = tid; e < 16 * 512; e += NT) {     // W_tau1 h-part, transposed
        int c = e >> 9, k = e & 511;
        sm[P_WT1 + c * W1_S + k] = __ldg(&W_tau1[(size_t)(512 + k) * 256 + zc0 + c]);
    }
    for (int e = tid; e < 32 * 512; e += NT) {     // W_rec rows
        int c = e >> 9, k = e & 511;
        sm[P_WREC + c * WR_S + k] = __ldg(&W_rec[(size_t)(hc0 + c) * 512 + k]);
    }
    for (int e = tid; e < 32 * 256; e += NT) {     // W_tau2 transposed
        int c = e >> 8, k = e & 255;
        sm[P_WT2 + c * W2_S + k] = __ldg(&W_tau2[(size_t)k * 512 + hc0 + c]);
    }
    if (tid < 16) sm[P_B1 + tid]   = b_tau1[zc0 + tid];
    if (tid < 32) sm[P_BIAS + tid] = bias[hc0 + tid];
    if (tid < 32) sm[P_B2 + tid]   = b_tau2[hc0 + tid];
    {
        int r = tid >> 5, c = tid & 31;
        __stcg(&g_h[(r0 + r) * H_ + hc0 + c], 0.f);
    }
    __syncthreads();
    CLUSTER_SYNC();

    const int rr = tid >> 5;      // 0..7
    const int cc = tid & 31;      // 0..31
    float drv = 0.f;

    for (int t = 0; t < T_; t++) {
        // ---- A0: stage h (8x512), xp diag (8x32), xq (8x16) ----
#pragma unroll
        for (int i = 0; i < 4; i++) {
            int idx = tid + 256 * i;
            int row = idx >> 7, q = idx & 127;
            float4 v = __ldcg((const float4*)&g_h[(r0 + row) * H_ + q * 4]);
            *(float4*)&sm[P_H + row * H_S + q * 4] = v;
        }
        if (tid < 64) {
            int row = tid >> 3, q = tid & 7;
            float4 v = __ldcg((const float4*)&g_xp[((size_t)(r0 + row) * T_ + t) * H_ + hc0 + q * 4]);
            *(float4*)&sm[P_XD + row * XD_S + q * 4] = v;
        } else if (tid < 96) {
            int i2 = tid - 64;
            int row = i2 >> 2, q = i2 & 3;
            float4 v = __ldcg((const float4*)&g_xq[((size_t)(r0 + row) * T_ + t) * 256 + zc0 + q * 4]);
            *(float4*)&sm[P_XQ + row * XQ_S + q * 4] = v;
        }
        __syncthreads();

        // ---- A2: drive partials (8r x 32c, k=512), 4x4 tiles, S=16 ----
        {
            const int s = tid & 15, tile = tid >> 4;
            const int tr = (tile & 1) * 4, tc = (tile >> 1) * 4;
            const float* wp = &sm[P_WREC + tc * WR_S];
            const float* ap = &sm[P_H + tr * H_S];
            unsigned long long acc[16];
#pragma unroll
            for (int e = 0; e < 16; e++) acc[e] = 0ull;
#pragma unroll
            for (int j = 0; j < 8; j++) {
                const int k = s * 4 + j * 64;
                unsigned long long w0[4], w1[4];
#pragma unroll
                for (int c = 0; c < 4; c++) {
                    double2 wv = *(const double2*)&wp[c * WR_S + k];
                    w0[c] = __double_as_longlong(wv.x);
                    w1[c] = __double_as_longlong(wv.y);
                }
#pragma unroll
                for (int i = 0; i < 4; i++) {
                    double2 av = *(const double2*)&ap[i * H_S + k];
                    unsigned long long a0 = __double_as_longlong(av.x);
                    unsigned long long a1 = __double_as_longlong(av.y);
#pragma unroll
                    for (int c = 0; c < 4; c++) {
                        fma2(acc[i * 4 + c], a0, w0[c]);
                        fma2(acc[i * 4 + c], a1, w1[c]);
                    }
                }
            }
#pragma unroll
            for (int i = 0; i < 4; i++)
#pragma unroll
                for (int c = 0; c < 4; c++)
                    sm[P_SCR + s * 257 + (tr + i) * 32 + tc + c] = pair_sum(acc[i * 4 + c]);
        }
        __syncthreads();

        // ---- drive reduce -> tanh ----
        {
            float pre = sm[P_XD + rr * XD_S + cc] + sm[P_BIAS + cc];
#pragma unroll
            for (int s = 0; s < 16; s++) pre += sm[P_SCR + s * 257 + rr * 32 + cc];
            float e2 = __expf(2.f * pre);
            drv = 1.f - 2.f / (e2 + 1.f);
        }
        __syncthreads();

        // ---- A1: z1 partials (8r x 16c, k=512), 4x4 tiles, S=32 ----
        {
            const int s = tid & 31, tile = tid >> 5;
            const int tr = (tile & 1) * 4, tc = (tile >> 1) * 4;
            const float* wp = &sm[P_WT1 + tc * W1_S];
            const float* ap = &sm[P_H + tr * H_S];
            unsigned long long acc[16];
#pragma unroll
            for (int e = 0; e < 16; e++) acc[e] = 0ull;
#pragma unroll
            for (int j = 0; j < 4; j++) {
                const int k = s * 4 + j * 128;
                unsigned long long w0[4], w1[4];
#pragma unroll
                for (int c = 0; c < 4; c++) {
                    double2 wv = *(const double2*)&wp[c * W1_S + k];
                    w0[c] = __double_as_longlong(wv.x);
                    w1[c] = __double_as_longlong(wv.y);
                }
#pragma unroll
                for (int i = 0; i < 4; i++) {
                    double2 av = *(const double2*)&ap[i * H_S + k];
                    unsigned long long a0 = __double_as_longlong(av.x);
                    unsigned long long a1 = __double_as_longlong(av.y);
#pragma unroll
                    for (int c = 0; c < 4; c++) {
                        fma2(acc[i * 4 + c], a0, w0[c]);
                        fma2(acc[i * 4 + c], a1, w1[c]);
                    }
                }
            }
#pragma unroll
            for (int i = 0; i < 4; i++)
#pragma unroll
                for (int c = 0; c < 4; c++)
                    sm[P_SCR + s * 129 + (tr + i) * 16 + tc + c] = pair_sum(acc[i * 4 + c]);
        }
        __syncthreads();

        // ---- z1 reduce + relu + store ----
        if (tid < 128) {
            int r = tid >> 4, c = tid & 15;
            float z = sm[P_B1 + c] + sm[P_XQ + r * XQ_S + c];
#pragma unroll
            for (int s = 0; s < 32; s++) z += sm[P_SCR + s * 129 + r * 16 + c];
            __stcg(&g_z1[(r0 + r) * 256 + zc0 + c], fmaxf(z, 0.f));
        }
        CLUSTER_SYNC();

        // ---- B0: stage full z1 (8x256) ----
#pragma unroll
        for (int i = 0; i < 2; i++) {
            int idx = tid + 256 * i;
            int row = idx >> 6, q = idx & 63;
            float4 v = __ldcg((const float4*)&g_z1[(r0 + row) * 256 + q * 4]);
            *(float4*)&sm[P_Z1 + row * Z1_S + q * 4] = v;
        }
        __syncthreads();

        // ---- B1: tau partials (8r x 32c, k=256), 4x4 tiles, S=16 ----
        {
            const int s = tid & 15, tile = tid >> 4;
            const int tr = (tile & 1) * 4, tc = (tile >> 1) * 4;
            const float* wp = &sm[P_WT2 + tc * W2_S];
            const float* ap = &sm[P_Z1 + tr * Z1_S];
            unsigned long long acc[16];
#pragma unroll
            for (int e = 0; e < 16; e++) acc[e] = 0ull;
#pragma unroll
            for (int j = 0; j < 4; j++) {
                const int k = s * 4 + j * 64;
                unsigned long long w0[4], w1[4];
#pragma unroll
                for (int c = 0; c < 4; c++) {
                    double2 wv = *(const double2*)&wp[c * W2_S + k];
                    w0[c] = __double_as_longlong(wv.x);
                    w1[c] = __double_as_longlong(wv.y);
                }
#pragma unroll
                for (int i = 0; i < 4; i++) {
                    double2 av = *(const double2*)&ap[i * Z1_S + k];
                    unsigned long long a0 = __double_as_longlong(av.x);
                    unsigned long long a1 = __double_as_longlong(av.y);
#pragma unroll
                    for (int c = 0; c < 4; c++) {
                        fma2(acc[i * 4 + c], a0, w0[c]);
                        fma2(acc[i * 4 + c], a1, w1[c]);
                    }
                }
            }
#pragma unroll
            for (int i = 0; i < 4; i++)
#pragma unroll
                for (int c = 0; c < 4; c++)
                    sm[P_SCR + s * 257 + (tr + i) * 32 + tc + c] = pair_sum(acc[i * 4 + c]);
        }
        __syncthreads();

        // ---- B2: tau reduce + Euler update ----
        {
            float sv = sm[P_B2 + cc];
#pragma unroll
            for (int s = 0; s < 16; s++) sv += sm[P_SCR + s * 257 + rr * 32 + cc];
            float sig = 1.f / (1.f + __expf(-sv));
            float tau = 5.f + sig * 45.f;
            float hold = sm[P_H + rr * H_S + hc0 + cc];
            float hnew = hold + (drv - hold) / tau;
            __stcg(&g_h[(r0 + rr) * H_ + hc0 + cc], hnew);
            __stcg(&g_hs[((size_t)(r0 + rr) * T_ + t) * H_ + hc0 + cc], hnew);
        }
        CLUSTER_SYNC();
    }
}

// ---------------- out = hs @ W_out + b_out ----------------------------------
__global__ void __launch_bounds__(256) out_gemm(const float* __restrict__ W_out,
                                                const float* __restrict__ b_out,
                                                float* __restrict__ out) {
    __shared__ float sw[H_ * 10];
    __shared__ float sb[10];
    for (int e = threadIdx.x; e < H_ * 10; e += 256) sw[e] = W_out[e];
    if (threadIdx.x < 10) sb[threadIdx.x] = b_out[threadIdx.x];
    __syncthreads();

    int wid = threadIdx.x >> 5, lane = threadIdx.x & 31;
    for (int row = blockIdx.x * 8 + wid; row < B_ * T_; row += gridDim.x * 8) {
        float h[16];
        const float* hp = &g_hs[(size_t)row * H_ + lane * 16];
#pragma unroll
        for (int i = 0; i < 4; i++) {
            float4 v = *(const float4*)&hp[i * 4];
            h[i * 4 + 0] = v.x; h[i * 4 + 1] = v.y;
            h[i * 4 + 2] = v.z; h[i * 4 + 3] = v.w;
        }
#pragma unroll
        for (int o = 0; o < 10; o++) {
            float p = 0.f;
#pragma unroll
            for (int i = 0; i < 16; i++) p += h[i] * sw[(lane * 16 + i) * 10 + o];
            p += __shfl_xor_sync(0xffffffff, p, 16);
            p += __shfl_xor_sync(0xffffffff, p, 8);
            p += __shfl_xor_sync(0xffffffff, p, 4);
            p += __shfl_xor_sync(0xffffffff, p, 2);
            p += __shfl_xor_sync(0xffffffff, p, 1);
            if (lane == 0) out[row * 10 + o] = p + sb[o];
        }
    }
}

// ---------------- launch -----------------------------------------------------
extern "C" void kernel_launch(void* const* d_in, const int* in_sizes, int n_in,
                              void* d_out, int out_size) {
    const float* x      = (const float*)d_in[0];
    const float* W_in   = (const float*)d_in[1];
    const float* b_in   = (const float*)d_in[2];
    const float* W_rec  = (const float*)d_in[3];
    const float* bias   = (const float*)d_in[4];
    const float* W_tau1 = (const float*)d_in[5];
    const float* b_tau1 = (const float*)d_in[6];
    const float* W_tau2 = (const float*)d_in[7];
    const float* b_tau2 = (const float*)d_in[8];
    const float* W_out  = (const float*)d_in[9];
    const float* b_out  = (const float*)d_in[10];
    float* out = (float*)d_out;

    float* d_xp; cudaGetSymbolAddress((void**)&d_xp, g_xp);
    float* d_xq; cudaGetSymbolAddress((void**)&d_xq, g_xq);
    float* d_weff; cudaGetSymbolAddress((void**)&d_weff, g_weff);
    float* d_beff; cudaGetSymbolAddress((void**)&d_beff, g_beff);

    cudaFuncSetAttribute(proj_gemm<H_>, cudaFuncAttributeMaxDynamicSharedMemorySize, XP_SMEM);
    cudaFuncSetAttribute(proj_gemm<256>, cudaFuncAttributeMaxDynamicSharedMemorySize, XP_SMEM);
    cudaFuncSetAttribute(scan_kernel, cudaFuncAttributeMaxDynamicSharedMemorySize, SCAN_SMEM);
    cudaFuncSetAttribute(scan_kernel, cudaFuncAttributeNonPortableClusterSizeAllowed, 1);

    weff_gemm<<<dim3(4, 2), 256>>>(W_in, W_tau1);
    beff_kernel<<<256, 64>>>(b_in, W_tau1, b_tau1);
    proj_gemm<H_><<<dim3(8, 1024), 256, XP_SMEM>>>(x, W_in, b_in, d_xp);
    proj_gemm<256><<<dim3(4, 1024), 256, XP_SMEM>>>(x, d_weff, d_beff, d_xq);
    scan_kernel<<<GRID_SCAN, NT, SCAN_SMEM>>>(W_rec, bias, W_tau1, b_tau1,
                                              W_tau2, b_tau2);
    out_gemm<<<2048, 256>>>(W_out, b_out, out);
}

// round 6
// speedup vs baseline: 2.2545x; 1.0948x over previous
#include <cuda_runtime.h>
#include <math.h>

#define B_ 64
#define T_ 1024
#define I_ 128
#define H_ 512

#define CLUSTER 16
#define GRID_SCAN 128
#define NT 256

// ---------------- device scratch (no allocations allowed) -------------------
__device__ float g_xp[B_ * T_ * H_];        // x @ W_in + b_in        [B,T,512]
__device__ float g_xq[B_ * T_ * (H_ / 2)];  // x @ W_eff + b_eff      [B,T,256]
__device__ float g_hs[B_ * T_ * H_];        // all hidden states      [B,T,512]
__device__ float g_weff[I_ * (H_ / 2)];     // W_in @ W_tau1[:512]    [128,256]
__device__ float g_beff[H_ / 2];            // b_in @ W1x + b_tau1    [256]

// ---------------- scan SMEM layout (floats) ---------------------------------
#define H_S   516
#define W1_S  516
#define WR_S  516
#define W2_S  260
#define Z1_S  260
#define HBUF  (8 * H_S)                       // 4128 floats per h buffer
constexpr int P_H0   = 0;                     // [8][516]  h buffer 0
constexpr int P_H1   = HBUF;                  // [8][516]  h buffer 1
constexpr int P_WT1  = 2 * HBUF;              // [16][516] W_tau1 h-part ^T
constexpr int P_WREC = P_WT1 + 16 * W1_S;     // [32][516] W_rec rows
constexpr int P_WT2  = P_WREC + 32 * WR_S;    // [32][260] W_tau2 ^T
constexpr int P_Z1   = P_WT2 + 32 * W2_S;     // [8][260]  full z1 (DSMEM-filled)
constexpr int P_SCR  = P_Z1 + 8 * Z1_S;       // [4128]    shared partials
constexpr int P_B1   = P_SCR + 4128;          // [16]
constexpr int P_BIAS = P_B1 + 16;             // [32]
constexpr int P_B2   = P_BIAS + 32;           // [32]
constexpr int SCAN_FLOATS = P_B2 + 32;
constexpr int SCAN_SMEM = SCAN_FLOATS * 4;    // ~186 KB

constexpr int XP_SMEM = (64 * 132 + 128 * 68) * 4;  // ~68.6 KB

// ---------------- helpers ----------------------------------------------------
__device__ __forceinline__ void fma2(unsigned long long& d,
                                     unsigned long long a,
                                     unsigned long long b) {
    asm("fma.rn.f32x2 %0, %1, %2, %0;" : "+l"(d) : "l"(a), "l"(b));
}
__device__ __forceinline__ float pair_sum(unsigned long long v) {
    return __uint_as_float((unsigned)v) + __uint_as_float((unsigned)(v >> 32));
}
__device__ __forceinline__ void st_cluster(unsigned addr, unsigned rank, float v) {
    unsigned ra;
    asm volatile("mapa.shared::cluster.u32 %0, %1, %2;" : "=r"(ra) : "r"(addr), "r"(rank));
    asm volatile("st.shared::cluster.f32 [%0], %1;" :: "r"(ra), "f"(v) : "memory");
}
#define CL_ARRIVE() asm volatile("barrier.cluster.arrive.aligned;" ::: "memory")
#define CL_WAIT()   asm volatile("barrier.cluster.wait.aligned;"   ::: "memory")
#define CLUSTER_SYNC() do { CL_ARRIVE(); CL_WAIT(); } while (0)

// ---------------- W_eff = W_in @ W_tau1[:512,:] ------------------------------
__global__ void __launch_bounds__(256) weff_gemm(const float* __restrict__ Win,
                                                 const float* __restrict__ Wt1) {
    __shared__ float sa[64 * 68];
    __shared__ float sb[64 * 68];
    const int tid = threadIdx.x;
    const int n0 = blockIdx.x * 64, m0 = blockIdx.y * 64;
    const int ty = tid >> 4, tx = tid & 15;
    float acc[4][4];
#pragma unroll
    for (int i = 0; i < 4; i++)
#pragma unroll
        for (int j = 0; j < 4; j++) acc[i][j] = 0.f;

    for (int kt = 0; kt < 512; kt += 64) {
        for (int f = tid; f < 64 * 16; f += 256) {
            int r = f >> 4, q = (f & 15) << 2;
            *(float4*)&sa[r * 68 + q] = *(const float4*)&Win[(size_t)(m0 + r) * 512 + kt + q];
            *(float4*)&sb[r * 68 + q] = *(const float4*)&Wt1[(size_t)(kt + r) * 256 + n0 + q];
        }
        __syncthreads();
#pragma unroll 8
        for (int k = 0; k < 64; k++) {
            float a[4];
#pragma unroll
            for (int i = 0; i < 4; i++) a[i] = sa[(ty * 4 + i) * 68 + k];
            float4 w = *(const float4*)&sb[k * 68 + tx * 4];
#pragma unroll
            for (int i = 0; i < 4; i++) {
                acc[i][0] += a[i] * w.x; acc[i][1] += a[i] * w.y;
                acc[i][2] += a[i] * w.z; acc[i][3] += a[i] * w.w;
            }
        }
        __syncthreads();
    }
#pragma unroll
    for (int i = 0; i < 4; i++) {
        float4 r;
        r.x = acc[i][0]; r.y = acc[i][1]; r.z = acc[i][2]; r.w = acc[i][3];
        *(float4*)&g_weff[(size_t)(m0 + ty * 4 + i) * 256 + n0 + tx * 4] = r;
    }
}

// ---------------- b_eff = b_in @ W1x + b_tau1 --------------------------------
__global__ void __launch_bounds__(64) beff_kernel(const float* __restrict__ b_in,
                                                  const float* __restrict__ Wt1,
                                                  const float* __restrict__ b_tau1) {
    __shared__ float red[64];
    const int c = blockIdx.x, lane = threadIdx.x;
    float p = 0.f;
    for (int k = lane; k < 512; k += 64) p += b_in[k] * Wt1[(size_t)k * 256 + c];
    red[lane] = p;
    __syncthreads();
    if (lane < 32) {
        float v = red[lane] + red[lane + 32];
        v += __shfl_xor_sync(0xffffffff, v, 16);
        v += __shfl_xor_sync(0xffffffff, v, 8);
        v += __shfl_xor_sync(0xffffffff, v, 4);
        v += __shfl_xor_sync(0xffffffff, v, 2);
        v += __shfl_xor_sync(0xffffffff, v, 1);
        if (lane == 0) g_beff[c] = v + b_tau1[c];
    }
}

// ---------------- generic projection: out = x @ W + b -----------------------
template <int NCOLS>
__global__ void __launch_bounds__(256) proj_gemm(const float* __restrict__ x,
                                                 const float* __restrict__ W,
                                                 const float* __restrict__ bvec,
                                                 float* __restrict__ outp) {
    extern __shared__ float sm[];
    float* sx = sm;                 // [64][132]
    float* sw = sm + 64 * 132;      // [128][68]
    const int tid = threadIdx.x;
    const int n0 = blockIdx.x * 64;
    const int r0 = blockIdx.y * 64;

    for (int f = tid; f < 64 * 32; f += 256) {
        int row = f >> 5, kq = (f & 31) << 2;
        *(float4*)(sx + row * 132 + kq) =
            *(const float4*)(x + (size_t)(r0 + row) * I_ + kq);
    }
    for (int f = tid; f < 128 * 16; f += 256) {
        int k = f >> 4, nq = (f & 15) << 2;
        *(float4*)(sw + k * 68 + nq) =
            *(const float4*)(W + (size_t)k * NCOLS + n0 + nq);
    }
    __syncthreads();

    const int ty = tid >> 4, tx = tid & 15;
    float acc[4][4];
#pragma unroll
    for (int i = 0; i < 4; i++)
#pragma unroll
        for (int j = 0; j < 4; j++) acc[i][j] = 0.f;

#pragma unroll 8
    for (int k = 0; k < 128; k++) {
        float a[4];
#pragma unroll
        for (int i = 0; i < 4; i++) a[i] = sx[(ty * 4 + i) * 132 + k];
        float4 w = *(const float4*)(sw + k * 68 + tx * 4);
#pragma unroll
        for (int i = 0; i < 4; i++) {
            acc[i][0] += a[i] * w.x; acc[i][1] += a[i] * w.y;
            acc[i][2] += a[i] * w.z; acc[i][3] += a[i] * w.w;
        }
    }

    float4 bv = *(const float4*)(bvec + n0 + tx * 4);
#pragma unroll
    for (int i = 0; i < 4; i++) {
        float4 r;
        r.x = acc[i][0] + bv.x; r.y = acc[i][1] + bv.y;
        r.z = acc[i][2] + bv.z; r.w = acc[i][3] + bv.w;
        *(float4*)(outp + (size_t)(r0 + ty * 4 + i) * NCOLS + n0 + tx * 4) = r;
    }
}

// ---------------- persistent clustered scan ----------------------------------
__global__ void __launch_bounds__(NT, 1) __cluster_dims__(CLUSTER, 1, 1)
scan_kernel(const float* __restrict__ W_rec, const float* __restrict__ bias,
            const float* __restrict__ W_tau1, const float* __restrict__ b_tau1,
            const float* __restrict__ W_tau2, const float* __restrict__ b_tau2) {
    extern __shared__ float sm[];
    const int tid = threadIdx.x;
    const int cid = blockIdx.x & (CLUSTER - 1);
    const int bg  = blockIdx.x >> 4;
    const int r0  = bg * 8;
    const int hc0 = cid * 32;
    const int zc0 = cid * 16;
    const unsigned sbase = (unsigned)__cvta_generic_to_shared(sm);

    // ---- one-time weight staging ----
    for (int e = tid; e < 16 * 512; e += NT) {     // W_tau1 h-part, transposed
        int c = e >> 9, k = e & 511;
        sm[P_WT1 + c * W1_S + k] = __ldg(&W_tau1[(size_t)(512 + k) * 256 + zc0 + c]);
    }
    for (int e = tid; e < 32 * 512; e += NT) {     // W_rec rows
        int c = e >> 9, k = e & 511;
        sm[P_WREC + c * WR_S + k] = __ldg(&W_rec[(size_t)(hc0 + c) * 512 + k]);
    }
    for (int e = tid; e < 32 * 256; e += NT) {     // W_tau2 transposed
        int c = e >> 8, k = e & 255;
        sm[P_WT2 + c * W2_S + k] = __ldg(&W_tau2[(size_t)k * 512 + hc0 + c]);
    }
    if (tid < 16) sm[P_B1 + tid]   = b_tau1[zc0 + tid];
    if (tid < 32) sm[P_BIAS + tid] = bias[hc0 + tid];
    if (tid < 32) sm[P_B2 + tid]   = b_tau2[hc0 + tid];
    // zero both h buffers
    for (int e = tid; e < 2 * HBUF; e += NT) sm[e] = 0.f;
    __syncthreads();
    CLUSTER_SYNC();

    const int rr = tid >> 5;      // 0..7 (h mapping)
    const int cc = tid & 31;      // 0..31
    const int zr = tid >> 4;      // z1 mapping (tid<128)
    const int zc = tid & 15;

    float xv  = __ldcg(&g_xp[((size_t)(r0 + rr) * T_) * H_ + hc0 + cc]);
    float xqv = 0.f;
    if (tid < 128)
        xqv = __ldcg(&g_xq[((size_t)(r0 + zr) * T_) * 256 + zc0 + zc]);

    float drv = 0.f;

    for (int t = 0; t < T_; t++) {
        const int pcur  = (t & 1) ? P_H1 : P_H0;
        const int pnext = (t & 1) ? P_H0 : P_H1;

        // ---- A1: z1 partials (8r x 16c, k=512), 4x4 tiles, S=32 ----
        {
            const int s = tid & 31, tile = tid >> 5;
            const int tr = (tile & 1) * 4, tc = (tile >> 1) * 4;
            const float* wp = &sm[P_WT1 + tc * W1_S];
            const float* ap = &sm[pcur + tr * H_S];
            unsigned long long acc[16];
#pragma unroll
            for (int e = 0; e < 16; e++) acc[e] = 0ull;
#pragma unroll
            for (int j = 0; j < 4; j++) {
                const int k = s * 4 + j * 128;
                unsigned long long w0[4], w1[4];
#pragma unroll
                for (int c = 0; c < 4; c++) {
                    double2 wv = *(const double2*)&wp[c * W1_S + k];
                    w0[c] = __double_as_longlong(wv.x);
                    w1[c] = __double_as_longlong(wv.y);
                }
#pragma unroll
                for (int i = 0; i < 4; i++) {
                    double2 av = *(const double2*)&ap[i * H_S + k];
                    unsigned long long a0 = __double_as_longlong(av.x);
                    unsigned long long a1 = __double_as_longlong(av.y);
#pragma unroll
                    for (int c = 0; c < 4; c++) {
                        fma2(acc[i * 4 + c], a0, w0[c]);
                        fma2(acc[i * 4 + c], a1, w1[c]);
                    }
                }
            }
#pragma unroll
            for (int i = 0; i < 4; i++)
#pragma unroll
                for (int c = 0; c < 4; c++)
                    sm[P_SCR + s * 129 + (tr + i) * 16 + tc + c] = pair_sum(acc[i * 4 + c]);
        }
        __syncthreads();

        // ---- z1 reduce + relu + DSMEM broadcast to whole cluster ----
        if (tid < 128) {
            float z = sm[P_B1 + zc] + xqv;
#pragma unroll
            for (int s = 0; s < 32; s++) z += sm[P_SCR + s * 129 + zr * 16 + zc];
            z = fmaxf(z, 0.f);
            unsigned a = sbase + (unsigned)(P_Z1 + zr * Z1_S + zc0 + zc) * 4u;
#pragma unroll
            for (unsigned rk = 0; rk < CLUSTER; rk++) st_cluster(a, rk, z);
        }
        __syncthreads();
        CL_ARRIVE();                       // (1) publish z1

        // ---- A2: drive partials (8r x 32c, k=512), 4x4 tiles, S=16 ----
        {
            const int s = tid & 15, tile = tid >> 4;
            const int tr = (tile & 1) * 4, tc = (tile >> 1) * 4;
            const float* wp = &sm[P_WREC + tc * WR_S];
            const float* ap = &sm[pcur + tr * H_S];
            unsigned long long acc[16];
#pragma unroll
            for (int e = 0; e < 16; e++) acc[e] = 0ull;
#pragma unroll
            for (int j = 0; j < 8; j++) {
                const int k = s * 4 + j * 64;
                unsigned long long w0[4], w1[4];
#pragma unroll
                for (int c = 0; c < 4; c++) {
                    double2 wv = *(const double2*)&wp[c * WR_S + k];
                    w0[c] = __double_as_longlong(wv.x);
                    w1[c] = __double_as_longlong(wv.y);
                }
#pragma unroll
                for (int i = 0; i < 4; i++) {
                    double2 av = *(const double2*)&ap[i * H_S + k];
                    unsigned long long a0 = __double_as_longlong(av.x);
                    unsigned long long a1 = __double_as_longlong(av.y);
#pragma unroll
                    for (int c = 0; c < 4; c++) {
                        fma2(acc[i * 4 + c], a0, w0[c]);
                        fma2(acc[i * 4 + c], a1, w1[c]);
                    }
                }
            }
#pragma unroll
            for (int i = 0; i < 4; i++)
#pragma unroll
                for (int c = 0; c < 4; c++)
                    sm[P_SCR + s * 257 + (tr + i) * 32 + tc + c] = pair_sum(acc[i * 4 + c]);
        }
        __syncthreads();

        // ---- drive reduce -> tanh ----
        {
            float pre = xv + sm[P_BIAS + cc];
#pragma unroll
            for (int s = 0; s < 16; s++) pre += sm[P_SCR + s * 257 + rr * 32 + cc];
            float e2 = __expf(2.f * pre);
            drv = 1.f - 2.f / (e2 + 1.f);
        }
        CL_WAIT();                         // (1) z1 now resident in local P_Z1
        __syncthreads();                   // protect P_SCR reuse

        // ---- B1: tau partials (8r x 32c, k=256), 4x4 tiles, S=16 ----
        {
            const int s = tid & 15, tile = tid >> 4;
            const int tr = (tile & 1) * 4, tc = (tile >> 1) * 4;
            const float* wp = &sm[P_WT2 + tc * W2_S];
            const float* ap = &sm[P_Z1 + tr * Z1_S];
            unsigned long long acc[16];
#pragma unroll
            for (int e = 0; e < 16; e++) acc[e] = 0ull;
#pragma unroll
            for (int j = 0; j < 4; j++) {
                const int k = s * 4 + j * 64;
                unsigned long long w0[4], w1[4];
#pragma unroll
                for (int c = 0; c < 4; c++) {
                    double2 wv = *(const double2*)&wp[c * W2_S + k];
                    w0[c] = __double_as_longlong(wv.x);
                    w1[c] = __double_as_longlong(wv.y);
                }
#pragma unroll
                for (int i = 0; i < 4; i++) {
                    double2 av = *(const double2*)&ap[i * Z1_S + k];
                    unsigned long long a0 = __double_as_longlong(av.x);
                    unsigned long long a1 = __double_as_longlong(av.y);
#pragma unroll
                    for (int c = 0; c < 4; c++) {
                        fma2(acc[i * 4 + c], a0, w0[c]);
                        fma2(acc[i * 4 + c], a1, w1[c]);
                    }
                }
            }
#pragma unroll
            for (int i = 0; i < 4; i++)
#pragma unroll
                for (int c = 0; c < 4; c++)
                    sm[P_SCR + s * 257 + (tr + i) * 32 + tc + c] = pair_sum(acc[i * 4 + c]);
        }
        __syncthreads();

        // ---- B2: tau reduce + Euler update + DSMEM h broadcast ----
        {
            float sv = sm[P_B2 + cc];
#pragma unroll
            for (int s = 0; s < 16; s++) sv += sm[P_SCR + s * 257 + rr * 32 + cc];
            float sig = 1.f / (1.f + __expf(-sv));
            float tau = 5.f + sig * 45.f;
            float hold = sm[pcur + rr * H_S + hc0 + cc];
            float hnew = hold + (drv - hold) / tau;
            unsigned a = sbase + (unsigned)(pnext + rr * H_S + hc0 + cc) * 4u;
#pragma unroll
            for (unsigned rk = 0; rk < CLUSTER; rk++) st_cluster(a, rk, hnew);
            __stcg(&g_hs[((size_t)(r0 + rr) * T_ + t) * H_ + hc0 + cc], hnew);
        }
        __syncthreads();
        CL_ARRIVE();                       // (2) publish h
        {
            int tn = (t + 1 < T_) ? t + 1 : t;          // prefetch next step
            xv = __ldcg(&g_xp[((size_t)(r0 + rr) * T_ + tn) * H_ + hc0 + cc]);
            if (tid < 128)
                xqv = __ldcg(&g_xq[((size_t)(r0 + zr) * T_ + tn) * 256 + zc0 + zc]);
        }
        CL_WAIT();                         // (2) h(t+1) resident
    }
}

// ---------------- out = hs @ W_out + b_out ----------------------------------
__global__ void __launch_bounds__(256) out_gemm(const float* __restrict__ W_out,
                                                const float* __restrict__ b_out,
                                                float* __restrict__ out) {
    __shared__ float sw[H_ * 10];
    __shared__ float sb[10];
    for (int e = threadIdx.x; e < H_ * 10; e += 256) sw[e] = W_out[e];
    if (threadIdx.x < 10) sb[threadIdx.x] = b_out[threadIdx.x];
    __syncthreads();

    int wid = threadIdx.x >> 5, lane = threadIdx.x & 31;
    for (int row = blockIdx.x * 8 + wid; row < B_ * T_; row += gridDim.x * 8) {
        float h[16];
        const float* hp = &g_hs[(size_t)row * H_ + lane * 16];
#pragma unroll
        for (int i = 0; i < 4; i++) {
            float4 v = *(const float4*)&hp[i * 4];
            h[i * 4 + 0] = v.x; h[i * 4 + 1] = v.y;
            h[i * 4 + 2] = v.z; h[i * 4 + 3] = v.w;
        }
#pragma unroll
        for (int o = 0; o < 10; o++) {
            float p = 0.f;
#pragma unroll
            for (int i = 0; i < 16; i++) p += h[i] * sw[(lane * 16 + i) * 10 + o];
            p += __shfl_xor_sync(0xffffffff, p, 16);
            p += __shfl_xor_sync(0xffffffff, p, 8);
            p += __shfl_xor_sync(0xffffffff, p, 4);
            p += __shfl_xor_sync(0xffffffff, p, 2);
            p += __shfl_xor_sync(0xffffffff, p, 1);
            if (lane == 0) out[row * 10 + o] = p + sb[o];
        }
    }
}

// ---------------- launch -----------------------------------------------------
extern "C" void kernel_launch(void* const* d_in, const int* in_sizes, int n_in,
                              void* d_out, int out_size) {
    const float* x      = (const float*)d_in[0];
    const float* W_in   = (const float*)d_in[1];
    const float* b_in   = (const float*)d_in[2];
    const float* W_rec  = (const float*)d_in[3];
    const float* bias   = (const float*)d_in[4];
    const float* W_tau1 = (const float*)d_in[5];
    const float* b_tau1 = (const float*)d_in[6];
    const float* W_tau2 = (const float*)d_in[7];
    const float* b_tau2 = (const float*)d_in[8];
    const float* W_out  = (const float*)d_in[9];
    const float* b_out  = (const float*)d_in[10];
    float* out = (float*)d_out;

    float* d_xp; cudaGetSymbolAddress((void**)&d_xp, g_xp);
    float* d_xq; cudaGetSymbolAddress((void**)&d_xq, g_xq);
    float* d_weff; cudaGetSymbolAddress((void**)&d_weff, g_weff);
    float* d_beff; cudaGetSymbolAddress((void**)&d_beff, g_beff);

    cudaFuncSetAttribute(proj_gemm<H_>, cudaFuncAttributeMaxDynamicSharedMemorySize, XP_SMEM);
    cudaFuncSetAttribute(proj_gemm<256>, cudaFuncAttributeMaxDynamicSharedMemorySize, XP_SMEM);
    cudaFuncSetAttribute(scan_kernel, cudaFuncAttributeMaxDynamicSharedMemorySize, SCAN_SMEM);
    cudaFuncSetAttribute(scan_kernel, cudaFuncAttributeNonPortableClusterSizeAllowed, 1);

    weff_gemm<<<dim3(4, 2), 256>>>(W_in, W_tau1);
    beff_kernel<<<256, 64>>>(b_in, W_tau1, b_tau1);
    proj_gemm<H_><<<dim3(8, 1024), 256, XP_SMEM>>>(x, W_in, b_in, d_xp);
    proj_gemm<256><<<dim3(4, 1024), 256, XP_SMEM>>>(x, d_weff, d_beff, d_xq);
    scan_kernel<<<GRID_SCAN, NT, SCAN_SMEM>>>(W_rec, bias, W_tau1, b_tau1,
                                              W_tau2, b_tau2);
    out_gemm<<<2048, 256>>>(W_out, b_out, out);
}